// round 7
// baseline (speedup 1.0000x reference)
#include <cuda_runtime.h>

#define TPB       512
#define ROWS_TILE 128                 // rows per row-tile
#define NSLICE    8                   // j-slices (512 j each)
#define CHUNKS    4                   // intra-CTA j-split: 128 row-slots x 4 chunks
#define NRT       128                 // row-tiles (batch 16384 / 128)
#define NUNITS    (NRT * NSLICE)      // 1024
#define JLEN      512                 // j per slice
#define JCHUNK    (JLEN / CHUNKS)     // 128 j per thread per unit
#define MAX_BATCH 16384

__device__ float g_partial[NSLICE][MAX_BATCH * 3];
__device__ int   g_cnt[NRT];

__global__ void __launch_bounds__(TPB, 1)
tps_main(const float* __restrict__ u,
         const float* __restrict__ cp,
         const float* __restrict__ w,
         const float* __restrict__ poly,
         float* __restrict__ out,
         int batch, int n) {
    __shared__ float4 s_c[JLEN];      // {-2cx,-2cy,-2cz,|c|^2}
    __shared__ float4 s_w[JLEN];      // {w0,w1,w2,0}
    __shared__ float  s_red[(CHUNKS - 1) * ROWS_TILE * 3];
    __shared__ int    s_flag;

    const int tid = threadIdx.x;
    const int bid = blockIdx.x;
    const int G   = gridDim.x;

    // Contiguous unit range for this persistent CTA (units are slice-major:
    // unit = slice*NRT + rt, so consecutive units share the staged slice).
    const int u0 = (int)(((long long)bid       * NUNITS) / G);
    const int u1 = (int)(((long long)(bid + 1) * NUNITS) / G);

    const int row_local = tid & (ROWS_TILE - 1);   // 0..127
    const int chunk     = tid >> 7;                // 0..3
    const int jb        = chunk * JCHUNK;

    int cur_slice = -1;

    for (int unit = u0; unit < u1; ++unit) {
        const int slice = unit >> 7;           // unit / NRT
        const int rt    = unit & (NRT - 1);    // unit % NRT

        __syncthreads();   // smem (s_c/s_w/s_red) safe to reuse

        if (slice != cur_slice) {
            const int j0g = slice * JLEN;
            if (tid < JLEN) {
                int j = j0g + tid;
                float cx = cp[3 * j + 0];
                float cy = cp[3 * j + 1];
                float cz = cp[3 * j + 2];
                float c2 = fmaf(cx, cx, fmaf(cy, cy, cz * cz));
                s_c[tid] = make_float4(-2.0f * cx, -2.0f * cy, -2.0f * cz, c2);
                s_w[tid] = make_float4(w[3 * j + 0], w[3 * j + 1], w[3 * j + 2], 0.0f);
            }
            cur_slice = slice;
            __syncthreads();
        }

        const int row = rt * ROWS_TILE + row_local;
        float ux = u[3 * row + 0];
        float uy = u[3 * row + 1];
        float uz = u[3 * row + 2];
        float u2 = fmaf(ux, ux, fmaf(uy, uy, uz * uz));

        float a0 = 0.0f, a1 = 0.0f, a2 = 0.0f;

        #pragma unroll 8
        for (int jj = jb; jj < jb + JCHUNK; ++jj) {
            float4 c  = s_c[jj];
            float4 wj = s_w[jj];
            // sq = |u|^2 + |c|^2 - 2 u.c  (expanded form, matches reference cdist)
            float sq = fmaf(c.x, ux, fmaf(c.y, uy, fmaf(c.z, uz, u2 + c.w)));
            sq = fmaxf(sq, 1e-20f);      // absorbs r<EPS -> 0 branch (k ~ -6.6e-9)
            float r, lg;
            asm("sqrt.approx.f32 %0, %1;" : "=f"(r)  : "f"(sq));
            asm("lg2.approx.f32 %0, %1;"  : "=f"(lg) : "f"(sq));
            float k = r * lg;            // true k = 0.5*ln2 * sqrt(sq)*lg2(sq)
            a0 = fmaf(k, wj.x, a0);
            a1 = fmaf(k, wj.y, a1);
            a2 = fmaf(k, wj.z, a2);
        }

        // Intra-CTA reduction over the 4 j-chunks.
        if (chunk > 0) {
            float* dst = &s_red[((chunk - 1) * ROWS_TILE + row_local) * 3];
            dst[0] = a0; dst[1] = a1; dst[2] = a2;
        }
        __syncthreads();

        if (chunk == 0) {
            #pragma unroll
            for (int cc = 0; cc < CHUNKS - 1; ++cc) {
                float* src = &s_red[(cc * ROWS_TILE + row_local) * 3];
                a0 += src[0]; a1 += src[1]; a2 += src[2];
            }
            float* gp = &g_partial[slice][3 * row];
            gp[0] = a0; gp[1] = a1; gp[2] = a2;
        }
        __threadfence();   // release partials before the counter signal
        __syncthreads();

        if (tid == 0)
            s_flag = (atomicAdd(&g_cnt[rt], 1) == NSLICE - 1);
        __syncthreads();

        if (s_flag) {
            __threadfence();   // acquire other CTAs' partials
            const float C = 0.34657359027997264f;   // 0.5 * ln(2)
            if (tid < ROWS_TILE * 3) {
                int rloc = tid / 3, comp = tid - 3 * rloc;
                int r2   = rt * ROWS_TILE + rloc;
                float sum = 0.0f;
                #pragma unroll
                for (int ss = 0; ss < NSLICE; ++ss)   // fixed order: deterministic
                    sum += g_partial[ss][3 * r2 + comp];
                float vx = u[3 * r2 + 0], vy = u[3 * r2 + 1], vz = u[3 * r2 + 2];
                float pp = poly[comp]
                         + fmaf(vx, poly[3 + comp],
                           fmaf(vy, poly[6 + comp], vz * poly[9 + comp]));
                out[3 * r2 + comp] = fmaf(C, sum, pp);
            }
            if (tid == 0) g_cnt[rt] = 0;   // self-reset for graph replay
        }
    }
}

extern "C" void kernel_launch(void* const* d_in, const int* in_sizes, int n_in,
                              void* d_out, int out_size) {
    const float* u    = (const float*)d_in[0];
    const float* cp   = (const float*)d_in[1];
    const float* w    = (const float*)d_in[2];
    const float* poly = (const float*)d_in[3];
    float* out = (float*)d_out;

    int batch = in_sizes[0] / 3;
    int n     = in_sizes[1] / 3;

    int sms = 148;
    cudaDeviceGetAttribute(&sms, cudaDevAttrMultiProcessorCount, 0);
    if (sms < 1) sms = 148;
    int blocks = sms;                 // 1 persistent CTA per SM, single wave

    tps_main<<<blocks, TPB>>>(u, cp, w, poly, out, batch, n);
}

// round 8
// speedup vs baseline: 1.2690x; 1.2690x over previous
#include <cuda_runtime.h>

#define TPB       512
#define NRT       128                  // row-tiles of 128 rows
#define ROWS_TILE 128
#define NJP       16                   // j-pieces of 256
#define JP_LEN    256
#define CHUNKS    4                    // intra-unit j split: 4 x 64 j
#define JSUB      64
#define NUNITS    (NRT * NJP)          // 2048
#define NPIECE    (NJP * CHUNKS)       // 64 partials per row
#define MAX_BATCH 16384

// Partial sums: piece p = jp*4+chunk covers j in [p*64, p*64+64).
__device__ float g_partial[NPIECE][MAX_BATCH * 3];   // 12.6 MB, L2-resident

__global__ void __launch_bounds__(TPB, 1)
tps_main(const float* __restrict__ u,
         const float* __restrict__ cp,
         const float* __restrict__ w,
         int batch, int n) {
    __shared__ float4 s_c[JP_LEN];     // {-2cx,-2cy,-2cz,|c|^2}
    __shared__ float4 s_w[JP_LEN];     // {w0,w1,w2,0}

    const int tid = threadIdx.x;
    const int bid = blockIdx.x;
    const int G   = gridDim.x;

    // Contiguous unit range, jp-major: unit = jp*NRT + rt.
    // Range length <= 14 < NRT, so at most one jp boundary per CTA.
    const int u0 = (int)(((long long)bid       * NUNITS) / G);
    const int u1 = (int)(((long long)(bid + 1) * NUNITS) / G);

    const int row_local = tid & (ROWS_TILE - 1);   // 0..127
    const int chunk     = tid >> 7;                // 0..3
    const int jb        = chunk * JSUB;

    int cur_jp = -1;

    for (int unit = u0; unit < u1; ++unit) {
        const int jp = unit >> 7;              // unit / NRT
        const int rt = unit & (NRT - 1);       // unit % NRT

        if (jp != cur_jp) {
            __syncthreads();                   // drain readers of old slice
            if (tid < JP_LEN) {
                int j = jp * JP_LEN + tid;
                float cx = cp[3 * j + 0];
                float cy = cp[3 * j + 1];
                float cz = cp[3 * j + 2];
                float c2 = fmaf(cx, cx, fmaf(cy, cy, cz * cz));
                s_c[tid] = make_float4(-2.0f * cx, -2.0f * cy, -2.0f * cz, c2);
                s_w[tid] = make_float4(w[3 * j + 0], w[3 * j + 1], w[3 * j + 2], 0.0f);
            }
            cur_jp = jp;
            __syncthreads();
        }

        const int row = rt * ROWS_TILE + row_local;
        float ux = u[3 * row + 0];
        float uy = u[3 * row + 1];
        float uz = u[3 * row + 2];
        float u2 = fmaf(ux, ux, fmaf(uy, uy, uz * uz));

        float a0 = 0.0f, a1 = 0.0f, a2 = 0.0f;

        #pragma unroll 8
        for (int jj = jb; jj < jb + JSUB; ++jj) {
            float4 c  = s_c[jj];
            float4 wj = s_w[jj];
            // sq = |u|^2 + |c|^2 - 2 u.c  (expanded form, matches reference cdist)
            float sq = fmaf(c.x, ux, fmaf(c.y, uy, fmaf(c.z, uz, u2 + c.w)));
            sq = fmaxf(sq, 1e-20f);       // absorbs r<EPS -> 0 branch (k ~ -6.6e-9)
            float r, lg;
            asm("sqrt.approx.f32 %0, %1;" : "=f"(r)  : "f"(sq));
            asm("lg2.approx.f32 %0, %1;"  : "=f"(lg) : "f"(sq));
            float k = r * lg;             // true k = 0.5*ln2 * sqrt(sq)*lg2(sq)
            a0 = fmaf(k, wj.x, a0);
            a1 = fmaf(k, wj.y, a1);
            a2 = fmaf(k, wj.z, a2);
        }

        // Independent partial: no reduction, no sync, no atomics.
        float* gp = &g_partial[jp * CHUNKS + chunk][3 * row];
        gp[0] = a0; gp[1] = a1; gp[2] = a2;
    }
}

__global__ void __launch_bounds__(256, 4)
tps_fixup(const float* __restrict__ u,
          const float* __restrict__ poly,
          float* __restrict__ out,
          int batch) {
    int idx = blockIdx.x * 256 + threadIdx.x;     // output element
    if (idx >= batch * 3) return;
    int row  = idx / 3;
    int comp = idx - 3 * row;

    float sum = 0.0f;
    #pragma unroll
    for (int p = 0; p < NPIECE; ++p)              // fixed order: deterministic
        sum += g_partial[p][idx];

    const float C = 0.34657359027997264f;         // 0.5 * ln(2)
    float vx = u[3 * row + 0], vy = u[3 * row + 1], vz = u[3 * row + 2];
    float pp = poly[comp]
             + fmaf(vx, poly[3 + comp],
               fmaf(vy, poly[6 + comp], vz * poly[9 + comp]));
    out[idx] = fmaf(C, sum, pp);
}

extern "C" void kernel_launch(void* const* d_in, const int* in_sizes, int n_in,
                              void* d_out, int out_size) {
    const float* u    = (const float*)d_in[0];
    const float* cp   = (const float*)d_in[1];
    const float* w    = (const float*)d_in[2];
    const float* poly = (const float*)d_in[3];
    float* out = (float*)d_out;

    int batch = in_sizes[0] / 3;
    int n     = in_sizes[1] / 3;

    int sms = 148;
    cudaDeviceGetAttribute(&sms, cudaDevAttrMultiProcessorCount, 0);
    if (sms < 1) sms = 148;

    tps_main<<<sms, TPB>>>(u, cp, w, batch, n);
    tps_fixup<<<(batch * 3 + 255) / 256, 256>>>(u, poly, out, batch);
}